// round 16
// baseline (speedup 1.0000x reference)
#include <cuda_runtime.h>
#include <cuda_fp16.h>
#include <cstdint>
#include <math.h>

#define EMB 1024
#define SEQ 2048
#define BATCH 2
#define NROWS 4096          // BATCH*SEQ
#define FFDIM 4096
#define NHEADS 16
#define HDIM 64

// -------------------- scratch (no allocation allowed) --------------------
__device__ unsigned short g_ln16 [NROWS * EMB];
__device__ unsigned short g_qkv16[(size_t)NROWS * 3 * EMB];
__device__ unsigned short g_ctx16[NROWS * EMB];
__device__ unsigned short g_ff16 [(size_t)NROWS * FFDIM];
__device__ float          g_x1   [NROWS * EMB];
__device__ unsigned short g_wqkv16[(size_t)EMB * 3 * EMB];
__device__ unsigned short g_wo16  [(size_t)EMB * EMB];
__device__ unsigned short g_wf116 [(size_t)EMB * FFDIM];
__device__ unsigned short g_wf216 [(size_t)FFDIM * EMB];

// -------------------- helpers --------------------
__device__ __forceinline__ float gelu_f(float v) {
    float u = v + 0.044715f * v * v * v;
    return 0.5f * v * (1.0f + tanhf(0.7978845608028654f * u));
}

__device__ __forceinline__ float ex2f(float x) {
    float r;
    asm("ex2.approx.f32 %0, %1;" : "=f"(r) : "f"(x));
    return r;
}

__device__ __forceinline__ uint32_t smem_u32(const void* p) {
    uint32_t a;
    asm("{ .reg .u64 t; cvta.to.shared.u64 t, %1; cvt.u32.u64 %0, t; }" : "=r"(a) : "l"(p));
    return a;
}

__device__ __forceinline__ unsigned packh2(float lo, float hi) {
    unsigned r;
    asm("cvt.rn.f16x2.f32 %0, %1, %2;" : "=r"(r) : "f"(hi), "f"(lo));
    return r;
}

__device__ __forceinline__ void mma16(float* c, const unsigned* a, const unsigned* b) {
    asm volatile(
        "mma.sync.aligned.m16n8k16.row.col.f32.f16.f16.f32 "
        "{%0,%1,%2,%3}, {%4,%5,%6,%7}, {%8,%9}, {%0,%1,%2,%3};\n"
        : "+f"(c[0]), "+f"(c[1]), "+f"(c[2]), "+f"(c[3])
        : "r"(a[0]), "r"(a[1]), "r"(a[2]), "r"(a[3]),
          "r"(b[0]), "r"(b[1]));
}

__device__ __forceinline__ void ldsm4(unsigned& r0, unsigned& r1, unsigned& r2, unsigned& r3,
                                      uint32_t addr) {
    asm volatile("ldmatrix.sync.aligned.m8n8.x4.shared.b16 {%0,%1,%2,%3}, [%4];"
                 : "=r"(r0), "=r"(r1), "=r"(r2), "=r"(r3) : "r"(addr));
}
__device__ __forceinline__ void ldsm4t(unsigned& r0, unsigned& r1, unsigned& r2, unsigned& r3,
                                       uint32_t addr) {
    asm volatile("ldmatrix.sync.aligned.m8n8.x4.trans.shared.b16 {%0,%1,%2,%3}, [%4];"
                 : "=r"(r0), "=r"(r1), "=r"(r2), "=r"(r3) : "r"(addr));
}

__device__ __forceinline__ void cpa16(uint32_t dst, const void* src) {
    asm volatile("cp.async.cg.shared.global [%0], [%1], 16;" :: "r"(dst), "l"(src));
}
#define CPA_COMMIT() asm volatile("cp.async.commit_group;" ::: "memory")
template<int N> __device__ __forceinline__ void cpa_wait() {
    asm volatile("cp.async.wait_group %0;" :: "n"(N) : "memory");
}

// -------------------- fused f32 -> f16 weight conversion (v2) --------------
#define ROUND2_BLOCKS 3072
__global__ void __launch_bounds__(256)
round_all2(const float* __restrict__ wq, const float* __restrict__ wk,
           const float* __restrict__ wv, const float* __restrict__ wo,
           const float* __restrict__ wf1, const float* __restrict__ wf2,
           __half* __restrict__ wqkv, __half* __restrict__ wo16,
           __half* __restrict__ wf116, __half* __restrict__ wf216)
{
    const int blk = blockIdx.x;
    const float* src;
    __half* dst;
    bool strided = false;
    int i;
    if (blk < 768) {
        int m = blk >> 8;
        src = (m == 0) ? wq : (m == 1) ? wk : wv;
        dst = wqkv + m * EMB;
        i = ((blk & 255) << 10) + threadIdx.x * 4;
        strided = true;
    } else if (blk < 1024) {
        src = wo;  dst = wo16;  i = ((blk - 768) << 10) + threadIdx.x * 4;
    } else if (blk < 2048) {
        src = wf1; dst = wf116; i = ((blk - 1024) << 10) + threadIdx.x * 4;
    } else {
        src = wf2; dst = wf216; i = ((blk - 2048) << 10) + threadIdx.x * 4;
    }

    const float4* s4 = (const float4*)src + i;
    float4 v0 = s4[0], v1 = s4[1], v2 = s4[2], v3 = s4[3];
    uint4 o0, o1;
    o0.x = packh2(v0.x, v0.y); o0.y = packh2(v0.z, v0.w);
    o0.z = packh2(v1.x, v1.y); o0.w = packh2(v1.z, v1.w);
    o1.x = packh2(v2.x, v2.y); o1.y = packh2(v2.z, v2.w);
    o1.z = packh2(v3.x, v3.y); o1.w = packh2(v3.z, v3.w);

    __half* d;
    if (strided) {
        int r = i >> 8;
        int c = (i & 255) << 2;
        d = dst + (size_t)r * (3 * EMB) + c;
    } else {
        d = dst + (size_t)i * 4;
    }
    *(uint4*)d = o0;
    *(uint4*)(d + 8) = o1;
}

// -------------------- layernorm (fp16 output) -------------------------------
__global__ void __launch_bounds__(256)
ln16_kernel(const float* __restrict__ x, const float* __restrict__ sc,
            const float* __restrict__ sh, __half* __restrict__ out)
{
    __shared__ float red[8];
    __shared__ float stats[2];
    const int row = blockIdx.x, tid = threadIdx.x, lane = tid & 31, warp = tid >> 5;
    const float* xr = x + (size_t)row * EMB;
    float4 v = *(const float4*)(xr + tid * 4);

    float s = v.x + v.y + v.z + v.w;
    #pragma unroll
    for (int o = 16; o > 0; o >>= 1) s += __shfl_xor_sync(0xffffffffu, s, o);
    if (lane == 0) red[warp] = s;
    __syncthreads();
    if (tid == 0) {
        float t = 0.f;
        #pragma unroll
        for (int i = 0; i < 8; i++) t += red[i];
        stats[0] = t * (1.0f / EMB);
    }
    __syncthreads();
    const float mean = stats[0];
    float dx = v.x - mean, dy = v.y - mean, dz = v.z - mean, dw = v.w - mean;
    float ss = dx * dx + dy * dy + dz * dz + dw * dw;
    #pragma unroll
    for (int o = 16; o > 0; o >>= 1) ss += __shfl_xor_sync(0xffffffffu, ss, o);
    if (lane == 0) red[warp] = ss;
    __syncthreads();
    if (tid == 0) {
        float t = 0.f;
        #pragma unroll
        for (int i = 0; i < 8; i++) t += red[i];
        stats[1] = rsqrtf(t * (1.0f / EMB) + 1e-5f);
    }
    __syncthreads();
    const float rstd = stats[1];
    float4 scv = *(const float4*)(sc + tid * 4);
    float4 shv = *(const float4*)(sh + tid * 4);
    __half2 h0 = __floats2half2_rn(scv.x * dx * rstd + shv.x, scv.y * dy * rstd + shv.y);
    __half2 h1 = __floats2half2_rn(scv.z * dz * rstd + shv.z, scv.w * dw * rstd + shv.w);
    __half2* o = (__half2*)(out + (size_t)row * EMB + tid * 4);
    o[0] = h0; o[1] = h1;
}

// -------------------- shared GEMM constants --------------------
#define BK 64
#define A_ROW_B 144
#define B_ROW_B 272

enum { EP_H = 0, EP_GELU_H = 1, EP_RES_F = 2 };

// ==================== GEMM small: 128x128, 128 thr, 2 CTA/SM ===============
#define BM 128
#define BN 128
#define ASTG (BM * A_ROW_B)
#define BSTG (BK * B_ROW_B)
#define STGB (ASTG + BSTG)
#define GEMM_SMEM (3 * STGB)

__device__ __forceinline__ void fill_stage16(uint32_t sA, uint32_t sB,
                                             const __half* __restrict__ A,
                                             const __half* __restrict__ B,
                                             int bm, int bn, int N, int K, int kc, int tid)
{
    #pragma unroll
    for (int i = 0; i < 8; i++) {
        int e = tid + i * 128;
        int row = e >> 3, seg = e & 7;
        cpa16(sA + row * A_ROW_B + seg * 16,
              A + (size_t)(bm + row) * K + kc * BK + seg * 8);
    }
    #pragma unroll
    for (int i = 0; i < 8; i++) {
        int e = tid + i * 128;
        int row = e >> 4, seg = e & 15;
        cpa16(sB + row * B_ROW_B + seg * 16,
              B + (size_t)(kc * BK + row) * N + bn + seg * 8);
    }
}

template<int EPI>
__global__ void __launch_bounds__(128, 2)
gemm16(const __half* __restrict__ A, const __half* __restrict__ B,
       const float* __restrict__ bias, const float* __restrict__ R,
       void* __restrict__ Cv, int M, int N, int K)
{
    extern __shared__ char smem[];
    const uint32_t sbase = smem_u32(smem);

    const int tid = threadIdx.x, lane = tid & 31, warp = tid >> 5;
    const int bm = blockIdx.y * BM, bn = blockIdx.x * BN;
    const int wm = (warp & 1) * 64, wn = (warp >> 1) * 64;
    const int g = lane >> 2, t = lane & 3;
    const int NK = K / BK;

    float c[4][8][4];
    #pragma unroll
    for (int mt = 0; mt < 4; mt++)
        #pragma unroll
        for (int nt = 0; nt < 8; nt++)
            #pragma unroll
            for (int e = 0; e < 4; e++) c[mt][nt][e] = 0.f;

    fill_stage16(sbase,        sbase + ASTG,        A, B, bm, bn, N, K, 0, tid);
    CPA_COMMIT();
    fill_stage16(sbase + STGB, sbase + STGB + ASTG, A, B, bm, bn, N, K, 1, tid);
    CPA_COMMIT();

    const uint32_t laoff = (wm + (lane & 15)) * A_ROW_B + (lane >> 4) * 16;
    const uint32_t lboff = (lane & 15) * B_ROW_B + (lane >> 4) * 16 + wn * 2;

    int stg = 0;
    for (int kt = 0; kt < NK; kt++) {
        if (kt == NK - 1) cpa_wait<0>(); else cpa_wait<1>();
        __syncthreads();

        if (kt + 2 < NK) {
            int fs = kt + 2; fs -= (fs / 3) * 3;
            fill_stage16(sbase + fs * STGB, sbase + fs * STGB + ASTG,
                         A, B, bm, bn, N, K, kt + 2, tid);
            CPA_COMMIT();
        }

        const uint32_t sA = sbase + stg * STGB;
        const uint32_t sB = sA + ASTG;
        const uint32_t la = sA + laoff;
        const uint32_t lb = sB + lboff;

        #pragma unroll
        for (int ks = 0; ks < 4; ks++) {
            unsigned a[4][4], b[8][2];
            #pragma unroll
            for (int mt = 0; mt < 4; mt++)
                ldsm4(a[mt][0], a[mt][1], a[mt][2], a[mt][3],
                      la + mt * (16 * A_ROW_B) + ks * 32);
            #pragma unroll
            for (int np = 0; np < 4; np++) {
                unsigned r0, r1, r2, r3;
                ldsm4t(r0, r1, r2, r3, lb + ks * (16 * B_ROW_B) + np * 32);
                b[2 * np][0] = r0;     b[2 * np][1] = r1;
                b[2 * np + 1][0] = r2; b[2 * np + 1][1] = r3;
            }
            #pragma unroll
            for (int mt = 0; mt < 4; mt++)
                #pragma unroll
                for (int nt = 0; nt < 8; nt++)
                    mma16(c[mt][nt], a[mt], b[nt]);
        }

        stg++; if (stg == 3) stg = 0;
    }

    #pragma unroll
    for (int mt = 0; mt < 4; mt++) {
        #pragma unroll
        for (int nt = 0; nt < 8; nt++) {
            const int row0 = bm + wm + mt * 16 + g;
            const int col  = bn + wn + nt * 8 + t * 2;
            #pragma unroll
            for (int h = 0; h < 2; h++) {
                const int row = row0 + h * 8;
                float v0 = c[mt][nt][2 * h], v1 = c[mt][nt][2 * h + 1];
                const size_t off = (size_t)row * N + col;
                if (EPI == EP_H) {
                    *(__half2*)((__half*)Cv + off) = __floats2half2_rn(v0, v1);
                } else if (EPI == EP_GELU_H) {
                    float2 bb = *(const float2*)(bias + col);
                    *(__half2*)((__half*)Cv + off) =
                        __floats2half2_rn(gelu_f(v0 + bb.x), gelu_f(v1 + bb.y));
                } else {
                    float2 bb = *(const float2*)(bias + col);
                    float2 rr = *(const float2*)(R + off);
                    *(float2*)((float*)Cv + off) =
                        make_float2(v0 + bb.x + rr.x, v1 + bb.y + rr.y);
                }
            }
        }
    }
}

// ==================== GEMM big: 256x128, 256 thr, 1 CTA/SM =================
#define BM2 256
#define ASTG2 (BM2 * A_ROW_B)
#define STGB2 (ASTG2 + BSTG)
#define GEMM2_SMEM (3 * STGB2)

__device__ __forceinline__ void fill_stage16b(uint32_t sA, uint32_t sB,
                                              const __half* __restrict__ A,
                                              const __half* __restrict__ B,
                                              int bm, int bn, int N, int K, int kc, int tid)
{
    #pragma unroll
    for (int i = 0; i < 8; i++) {
        int e = tid + i * 256;
        int row = e >> 3, seg = e & 7;
        cpa16(sA + row * A_ROW_B + seg * 16,
              A + (size_t)(bm + row) * K + kc * BK + seg * 8);
    }
    #pragma unroll
    for (int i = 0; i < 4; i++) {
        int e = tid + i * 256;
        int row = e >> 4, seg = e & 15;
        cpa16(sB + row * B_ROW_B + seg * 16,
              B + (size_t)(kc * BK + row) * N + bn + seg * 8);
    }
}

template<int EPI>
__global__ void __launch_bounds__(256, 1)
gemm16b(const __half* __restrict__ A, const __half* __restrict__ B,
        const float* __restrict__ bias, const float* __restrict__ R,
        void* __restrict__ Cv, int M, int N, int K)
{
    extern __shared__ char smem[];
    const uint32_t sbase = smem_u32(smem);

    const int tid = threadIdx.x, lane = tid & 31, warp = tid >> 5;
    const int bm = blockIdx.y * BM2, bn = blockIdx.x * BN;
    const int wm = (warp & 3) * 64, wn = (warp >> 2) * 64;
    const int g = lane >> 2, t = lane & 3;
    const int NK = K / BK;

    float c[4][8][4];
    #pragma unroll
    for (int mt = 0; mt < 4; mt++)
        #pragma unroll
        for (int nt = 0; nt < 8; nt++)
            #pragma unroll
            for (int e = 0; e < 4; e++) c[mt][nt][e] = 0.f;

    fill_stage16b(sbase,         sbase + ASTG2,         A, B, bm, bn, N, K, 0, tid);
    CPA_COMMIT();
    fill_stage16b(sbase + STGB2, sbase + STGB2 + ASTG2, A, B, bm, bn, N, K, 1, tid);
    CPA_COMMIT();

    const uint32_t laoff = (wm + (lane & 15)) * A_ROW_B + (lane >> 4) * 16;
    const uint32_t lboff = (lane & 15) * B_ROW_B + (lane >> 4) * 16 + wn * 2;

    int stg = 0;
    for (int kt = 0; kt < NK; kt++) {
        if (kt == NK - 1) cpa_wait<0>(); else cpa_wait<1>();
        __syncthreads();

        if (kt + 2 < NK) {
            int fs = kt + 2; fs -= (fs / 3) * 3;
            fill_stage16b(sbase + fs * STGB2, sbase + fs * STGB2 + ASTG2,
                          A, B, bm, bn, N, K, kt + 2, tid);
            CPA_COMMIT();
        }

        const uint32_t sA = sbase + stg * STGB2;
        const uint32_t sB = sA + ASTG2;
        const uint32_t la = sA + laoff;
        const uint32_t lb = sB + lboff;

        #pragma unroll
        for (int ks = 0; ks < 4; ks++) {
            unsigned a[4][4], b[8][2];
            #pragma unroll
            for (int mt = 0; mt < 4; mt++)
                ldsm4(a[mt][0], a[mt][1], a[mt][2], a[mt][3],
                      la + mt * (16 * A_ROW_B) + ks * 32);
            #pragma unroll
            for (int np = 0; np < 4; np++) {
                unsigned r0, r1, r2, r3;
                ldsm4t(r0, r1, r2, r3, lb + ks * (16 * B_ROW_B) + np * 32);
                b[2 * np][0] = r0;     b[2 * np][1] = r1;
                b[2 * np + 1][0] = r2; b[2 * np + 1][1] = r3;
            }
            #pragma unroll
            for (int mt = 0; mt < 4; mt++)
                #pragma unroll
                for (int nt = 0; nt < 8; nt++)
                    mma16(c[mt][nt], a[mt], b[nt]);
        }

        stg++; if (stg == 3) stg = 0;
    }

    #pragma unroll
    for (int mt = 0; mt < 4; mt++) {
        #pragma unroll
        for (int nt = 0; nt < 8; nt++) {
            const int row0 = bm + wm + mt * 16 + g;
            const int col  = bn + wn + nt * 8 + t * 2;
            #pragma unroll
            for (int h = 0; h < 2; h++) {
                const int row = row0 + h * 8;
                float v0 = c[mt][nt][2 * h], v1 = c[mt][nt][2 * h + 1];
                const size_t off = (size_t)row * N + col;
                if (EPI == EP_H) {
                    *(__half2*)((__half*)Cv + off) = __floats2half2_rn(v0, v1);
                } else if (EPI == EP_GELU_H) {
                    float2 bb = *(const float2*)(bias + col);
                    *(__half2*)((__half*)Cv + off) =
                        __floats2half2_rn(gelu_f(v0 + bb.x), gelu_f(v1 + bb.y));
                } else {
                    float2 bb = *(const float2*)(bias + col);
                    float2 rr = *(const float2*)(R + off);
                    *(float2*)((float*)Cv + off) =
                        make_float2(v0 + bb.x + rr.x, v1 + bb.y + rr.y);
                }
            }
        }
    }
}

// -------------------- fp16 causal flash attention (Br=128, Bc=64, d=64) ----
// 256 threads / 8 warps per CTA (each warp owns 16 query rows). One K/V fill
// serves 128 query rows; 3-stage KV ring -> one barrier per tile.
// exp2-domain softmax, scale folded into Q. Per-row math identical to Bc=64
// Br=64 version (same j-tile sequence) -> bit-identical results.
#define KROW 144
#define KVSTG (2 * 64 * KROW)                 // K + V per 64-row tile = 18432
#define ATT_SMEM (128 * KROW + 3 * KVSTG)     // Q(18432) + 3 stages = 73728

__global__ void __launch_bounds__(256, 1)
attn16(const __half* __restrict__ Qg, const __half* __restrict__ Kg,
       const __half* __restrict__ Vg, __half* __restrict__ O, int ldq)
{
    extern __shared__ char smem[];
    const uint32_t sbase = smem_u32(smem);
    const uint32_t sQ = sbase;
    const uint32_t sKV0 = sbase + 128 * KROW;

    const int tid = threadIdx.x, lane = tid & 31, warp = tid >> 5;
    const int g = lane >> 2, t = lane & 3;

    const int qt = gridDim.x - 1 - blockIdx.x;   // big tiles first
    const int bh = blockIdx.y;
    const int b = bh >> 4, h = bh & 15;
    const size_t qbase = (size_t)b * SEQ * ldq + (size_t)h * HDIM;
    const size_t obase = (size_t)b * SEQ * EMB + (size_t)h * HDIM;

    const int njt = 2 * qt + 2;                  // 64-col K tiles

    // fill 64-row K/V tile j into ring stage s
    auto fill_kv = [&](int s, int j) {
        const uint32_t sK = sKV0 + s * KVSTG;
        const uint32_t sV = sK + 64 * KROW;
        #pragma unroll
        for (int i = 0; i < 2; i++) {
            int e = tid + i * 256;
            int row = e >> 3, seg = e & 7;
            size_t go = qbase + (size_t)(j * 64 + row) * ldq + seg * 8;
            cpa16(sK + row * KROW + seg * 16, Kg + go);
            cpa16(sV + row * KROW + seg * 16, Vg + go);
        }
    };

    fill_kv(0, 0);
    CPA_COMMIT();
    fill_kv(1, 1);
    CPA_COMMIT();

    // Q tile (128 rows) -> smem, scaled by 0.125*log2(e)
    const __half2 qsc = __half2half2(__float2half(0.18033688f));
    #pragma unroll
    for (int i = 0; i < 4; i++) {
        int e = tid + i * 256;
        int row = e >> 3, seg = e & 7;
        uint4 raw = *(const uint4*)(Qg + qbase + (size_t)(qt * 128 + row) * ldq + seg * 8);
        __half2* hp = (__half2*)&raw;
        hp[0] = __hmul2(hp[0], qsc);
        hp[1] = __hmul2(hp[1], qsc);
        hp[2] = __hmul2(hp[2], qsc);
        hp[3] = __hmul2(hp[3], qsc);
        *(uint4*)(smem + row * KROW + seg * 16) = raw;
    }
    __syncthreads();

    unsigned qa[4][4];
    {
        const uint32_t la = sQ + (warp * 16 + (lane & 15)) * KROW + (lane >> 4) * 16;
        #pragma unroll
        for (int ks = 0; ks < 4; ks++)
            ldsm4(qa[ks][0], qa[ks][1], qa[ks][2], qa[ks][3], la + ks * 32);
    }

    const uint32_t kboff = ((lane & 7) + ((lane >> 4) << 3)) * KROW + ((lane >> 3) & 1) * 16;
    const uint32_t vboff = (lane & 15) * KROW + (lane >> 4) * 16;

    float m0 = -1e30f, m1 = -1e30f, l0 = 0.f, l1 = 0.f;
    float o[8][4];
    #pragma unroll
    for (int dt = 0; dt < 8; dt++)
        #pragma unroll
        for (int e = 0; e < 4; e++) o[dt][e] = 0.f;

    const int r0g = qt * 128 + warp * 16 + g;

    int stg = 0;
    for (int j = 0; j < njt; j++) {
        // ensure fill(j) landed (allow fill(j+1) in flight)
        if (j + 1 < njt) cpa_wait<1>(); else cpa_wait<0>();
        __syncthreads();   // all warps done with stage from iter j-1 -> safe to refill

        if (j + 2 < njt) {
            int fs = stg + 2; if (fs >= 3) fs -= 3;   // == (j-1) mod 3, freed by barrier
            fill_kv(fs, j + 2);
            CPA_COMMIT();
        }

        const uint32_t sK = sKV0 + stg * KVSTG;
        const uint32_t sV = sK + 64 * KROW;

        float s[8][4];
        #pragma unroll
        for (int nt = 0; nt < 8; nt++)
            #pragma unroll
            for (int e = 0; e < 4; e++) s[nt][e] = 0.f;

        #pragma unroll
        for (int ks = 0; ks < 4; ks++) {
            unsigned kb[8][2];
            #pragma unroll
            for (int np = 0; np < 4; np++) {
                unsigned r0, r1, r2, r3;
                ldsm4(r0, r1, r2, r3, sK + kboff + np * (16 * KROW) + ks * 32);
                kb[2 * np][0] = r0;     kb[2 * np][1] = r1;
                kb[2 * np + 1][0] = r2; kb[2 * np + 1][1] = r3;
            }
            #pragma unroll
            for (int nt = 0; nt < 8; nt++)
                mma16(s[nt], qa[ks], kb[nt]);
        }

        // causal mask on the last two tiles (element-wise, exact)
        if (j >= njt - 2) {
            #pragma unroll
            for (int nt = 0; nt < 8; nt++) {
                int cb = j * 64 + nt * 8 + t * 2;
                if (cb     > r0g)     s[nt][0] = -1e30f;
                if (cb + 1 > r0g)     s[nt][1] = -1e30f;
                if (cb     > r0g + 8) s[nt][2] = -1e30f;
                if (cb + 1 > r0g + 8) s[nt][3] = -1e30f;
            }
        }

        float t0 = -1e30f, t1 = -1e30f;
        #pragma unroll
        for (int nt = 0; nt < 8; nt++) {
            t0 = fmaxf(t0, fmaxf(s[nt][0], s[nt][1]));
            t1 = fmaxf(t1, fmaxf(s[nt][2], s[nt][3]));
        }
        t0 = fmaxf(t0, __shfl_xor_sync(0xffffffffu, t0, 1));
        t0 = fmaxf(t0, __shfl_xor_sync(0xffffffffu, t0, 2));
        t1 = fmaxf(t1, __shfl_xor_sync(0xffffffffu, t1, 1));
        t1 = fmaxf(t1, __shfl_xor_sync(0xffffffffu, t1, 2));
        float mn0 = fmaxf(m0, t0), mn1 = fmaxf(m1, t1);
        float al0 = ex2f(m0 - mn0), al1 = ex2f(m1 - mn1);
        float su0 = 0.f, su1 = 0.f;
        #pragma unroll
        for (int nt = 0; nt < 8; nt++) {
            s[nt][0] = ex2f(s[nt][0] - mn0); su0 += s[nt][0];
            s[nt][1] = ex2f(s[nt][1] - mn0); su0 += s[nt][1];
            s[nt][2] = ex2f(s[nt][2] - mn1); su1 += s[nt][2];
            s[nt][3] = ex2f(s[nt][3] - mn1); su1 += s[nt][3];
        }
        su0 += __shfl_xor_sync(0xffffffffu, su0, 1);
        su0 += __shfl_xor_sync(0xffffffffu, su0, 2);
        su1 += __shfl_xor_sync(0xffffffffu, su1, 1);
        su1 += __shfl_xor_sync(0xffffffffu, su1, 2);
        l0 = l0 * al0 + su0; l1 = l1 * al1 + su1;
        m0 = mn0; m1 = mn1;
        #pragma unroll
        for (int dt = 0; dt < 8; dt++) {
            o[dt][0] *= al0; o[dt][1] *= al0;
            o[dt][2] *= al1; o[dt][3] *= al1;
        }

        #pragma unroll
        for (int ks = 0; ks < 4; ks++) {
            unsigned pa[4];
            pa[0] = packh2(s[2 * ks][0],     s[2 * ks][1]);
            pa[1] = packh2(s[2 * ks][2],     s[2 * ks][3]);
            pa[2] = packh2(s[2 * ks + 1][0], s[2 * ks + 1][1]);
            pa[3] = packh2(s[2 * ks + 1][2], s[2 * ks + 1][3]);
            unsigned vb[8][2];
            #pragma unroll
            for (int np = 0; np < 4; np++) {
                unsigned r0, r1, r2, r3;
                ldsm4t(r0, r1, r2, r3, sV + vboff + ks * (16 * KROW) + np * 32);
                vb[2 * np][0] = r0;     vb[2 * np][1] = r1;
                vb[2 * np + 1][0] = r2; vb[2 * np + 1][1] = r3;
            }
            #pragma unroll
            for (int nt = 0; nt < 8; nt++)
                mma16(o[nt], pa, vb[nt]);
        }

        stg++; if (stg == 3) stg = 0;
        // no trailing barrier: 3-stage ring + top barrier protect reuse
    }

    const float i0 = 1.0f / l0, i1 = 1.0f / l1;
    #pragma unroll
    for (int dt = 0; dt < 8; dt++) {
        int col = dt * 8 + t * 2;
        size_t off0 = obase + (size_t)r0g * EMB + col;
        size_t off1 = obase + (size_t)(r0g + 8) * EMB + col;
        *(__half2*)(O + off0) = __floats2half2_rn(o[dt][0] * i0, o[dt][1] * i0);
        *(__half2*)(O + off1) = __floats2half2_rn(o[dt][2] * i1, o[dt][3] * i1);
    }
}

// -------------------- launch --------------------
extern "C" void kernel_launch(void* const* d_in, const int* in_sizes, int n_in,
                              void* d_out, int out_size)
{
    const float* x     = (const float*)d_in[0];
    const float* w_q   = (const float*)d_in[1];
    const float* w_k   = (const float*)d_in[2];
    const float* w_v   = (const float*)d_in[3];
    const float* w_o   = (const float*)d_in[4];
    const float* b_o   = (const float*)d_in[5];
    const float* ln1s  = (const float*)d_in[6];
    const float* ln1b  = (const float*)d_in[7];
    const float* ln2s  = (const float*)d_in[8];
    const float* ln2b  = (const float*)d_in[9];
    const float* w_ff1 = (const float*)d_in[10];
    const float* b_ff1 = (const float*)d_in[11];
    const float* w_ff2 = (const float*)d_in[12];
    const float* b_ff2 = (const float*)d_in[13];
    float* out = (float*)d_out;

    void *p;
    cudaGetSymbolAddress(&p, g_ln16);   __half* ln16   = (__half*)p;
    cudaGetSymbolAddress(&p, g_qkv16);  __half* qkv16  = (__half*)p;
    cudaGetSymbolAddress(&p, g_ctx16);  __half* ctx16  = (__half*)p;
    cudaGetSymbolAddress(&p, g_ff16);   __half* ff16   = (__half*)p;
    cudaGetSymbolAddress(&p, g_x1);     float*  x1     = (float*)p;
    cudaGetSymbolAddress(&p, g_wqkv16); __half* wqkv16 = (__half*)p;
    cudaGetSymbolAddress(&p, g_wo16);   __half* wo16   = (__half*)p;
    cudaGetSymbolAddress(&p, g_wf116);  __half* wf116  = (__half*)p;
    cudaGetSymbolAddress(&p, g_wf216);  __half* wf216  = (__half*)p;

    cudaFuncSetAttribute((const void*)gemm16<EP_RES_F>,
                         cudaFuncAttributeMaxDynamicSharedMemorySize, GEMM_SMEM);
    cudaFuncSetAttribute((const void*)gemm16b<EP_H>,
                         cudaFuncAttributeMaxDynamicSharedMemorySize, GEMM2_SMEM);
    cudaFuncSetAttribute((const void*)gemm16b<EP_GELU_H>,
                         cudaFuncAttributeMaxDynamicSharedMemorySize, GEMM2_SMEM);
    cudaFuncSetAttribute((const void*)attn16,
                         cudaFuncAttributeMaxDynamicSharedMemorySize, ATT_SMEM);

    // weights -> fp16, single fast launch
    round_all2<<<ROUND2_BLOCKS, 256>>>(w_q, w_k, w_v, w_o, w_ff1, w_ff2,
                                       wqkv16, wo16, wf116, wf216);

    // h = LN1(x)
    ln16_kernel<<<NROWS, 256>>>(x, ln1s, ln1b, ln16);
    // qkv = h @ [Wq|Wk|Wv]
    gemm16b<EP_H><<<dim3(3 * EMB / BN, NROWS / BM2), 256, GEMM2_SMEM>>>(
        ln16, wqkv16, nullptr, nullptr, qkv16, NROWS, 3 * EMB, EMB);
    // ctx = causal attention (Br=128 CTAs)
    attn16<<<dim3(SEQ / 128, BATCH * NHEADS), 256, ATT_SMEM>>>(
        qkv16, qkv16 + EMB, qkv16 + 2 * EMB, ctx16, 3 * EMB);
    // x1 = x + ctx @ w_o + b_o
    gemm16<EP_RES_F><<<dim3(EMB / BN, NROWS / BM), 128, GEMM_SMEM>>>(
        ctx16, wo16, b_o, x, x1, NROWS, EMB, EMB);
    // h = LN2(x1)
    ln16_kernel<<<NROWS, 256>>>(x1, ln2s, ln2b, ln16);
    // ff = gelu(h @ w_ff1 + b_ff1)
    gemm16b<EP_GELU_H><<<dim3(FFDIM / BN, NROWS / BM2), 256, GEMM2_SMEM>>>(
        ln16, wf116, b_ff1, nullptr, ff16, NROWS, FFDIM, EMB);
    // out = x1 + ff @ w_ff2 + b_ff2
    gemm16<EP_RES_F><<<dim3(EMB / BN, NROWS / BM), 128, GEMM_SMEM>>>(
        ff16, wf216, b_ff2, x1, out, NROWS, EMB, FFDIM);
}

// round 17
// speedup vs baseline: 1.5864x; 1.5864x over previous
#include <cuda_runtime.h>
#include <cuda_fp16.h>
#include <cstdint>
#include <math.h>

#define EMB 1024
#define SEQ 2048
#define BATCH 2
#define NROWS 4096          // BATCH*SEQ
#define FFDIM 4096
#define NHEADS 16
#define HDIM 64

// -------------------- scratch (no allocation allowed) --------------------
__device__ unsigned short g_ln16 [NROWS * EMB];
__device__ unsigned short g_qkv16[(size_t)NROWS * 3 * EMB];
__device__ unsigned short g_ctx16[NROWS * EMB];
__device__ unsigned short g_ff16 [(size_t)NROWS * FFDIM];
__device__ float          g_x1   [NROWS * EMB];
__device__ unsigned short g_wqkv16[(size_t)EMB * 3 * EMB];
__device__ unsigned short g_wo16  [(size_t)EMB * EMB];
__device__ unsigned short g_wf116 [(size_t)EMB * FFDIM];
__device__ unsigned short g_wf216 [(size_t)FFDIM * EMB];

// -------------------- helpers --------------------
__device__ __forceinline__ float gelu_f(float v) {
    float u = v + 0.044715f * v * v * v;
    return 0.5f * v * (1.0f + tanhf(0.7978845608028654f * u));
}

__device__ __forceinline__ float ex2f(float x) {
    float r;
    asm("ex2.approx.f32 %0, %1;" : "=f"(r) : "f"(x));
    return r;
}

__device__ __forceinline__ uint32_t smem_u32(const void* p) {
    uint32_t a;
    asm("{ .reg .u64 t; cvta.to.shared.u64 t, %1; cvt.u32.u64 %0, t; }" : "=r"(a) : "l"(p));
    return a;
}

__device__ __forceinline__ unsigned packh2(float lo, float hi) {
    unsigned r;
    asm("cvt.rn.f16x2.f32 %0, %1, %2;" : "=r"(r) : "f"(hi), "f"(lo));
    return r;
}

__device__ __forceinline__ void mma16(float* c, const unsigned* a, const unsigned* b) {
    asm volatile(
        "mma.sync.aligned.m16n8k16.row.col.f32.f16.f16.f32 "
        "{%0,%1,%2,%3}, {%4,%5,%6,%7}, {%8,%9}, {%0,%1,%2,%3};\n"
        : "+f"(c[0]), "+f"(c[1]), "+f"(c[2]), "+f"(c[3])
        : "r"(a[0]), "r"(a[1]), "r"(a[2]), "r"(a[3]),
          "r"(b[0]), "r"(b[1]));
}

__device__ __forceinline__ void ldsm4(unsigned& r0, unsigned& r1, unsigned& r2, unsigned& r3,
                                      uint32_t addr) {
    asm volatile("ldmatrix.sync.aligned.m8n8.x4.shared.b16 {%0,%1,%2,%3}, [%4];"
                 : "=r"(r0), "=r"(r1), "=r"(r2), "=r"(r3) : "r"(addr));
}
__device__ __forceinline__ void ldsm4t(unsigned& r0, unsigned& r1, unsigned& r2, unsigned& r3,
                                       uint32_t addr) {
    asm volatile("ldmatrix.sync.aligned.m8n8.x4.trans.shared.b16 {%0,%1,%2,%3}, [%4];"
                 : "=r"(r0), "=r"(r1), "=r"(r2), "=r"(r3) : "r"(addr));
}

__device__ __forceinline__ void cpa16(uint32_t dst, const void* src) {
    asm volatile("cp.async.cg.shared.global [%0], [%1], 16;" :: "r"(dst), "l"(src));
}
#define CPA_COMMIT() asm volatile("cp.async.commit_group;" ::: "memory")
template<int N> __device__ __forceinline__ void cpa_wait() {
    asm volatile("cp.async.wait_group %0;" :: "n"(N) : "memory");
}

// -------------------- fused f32 -> f16 weight conversion (v2) --------------
#define ROUND2_BLOCKS 3072
__global__ void __launch_bounds__(256)
round_all2(const float* __restrict__ wq, const float* __restrict__ wk,
           const float* __restrict__ wv, const float* __restrict__ wo,
           const float* __restrict__ wf1, const float* __restrict__ wf2,
           __half* __restrict__ wqkv, __half* __restrict__ wo16,
           __half* __restrict__ wf116, __half* __restrict__ wf216)
{
    const int blk = blockIdx.x;
    const float* src;
    __half* dst;
    bool strided = false;
    int i;
    if (blk < 768) {
        int m = blk >> 8;
        src = (m == 0) ? wq : (m == 1) ? wk : wv;
        dst = wqkv + m * EMB;
        i = ((blk & 255) << 10) + threadIdx.x * 4;
        strided = true;
    } else if (blk < 1024) {
        src = wo;  dst = wo16;  i = ((blk - 768) << 10) + threadIdx.x * 4;
    } else if (blk < 2048) {
        src = wf1; dst = wf116; i = ((blk - 1024) << 10) + threadIdx.x * 4;
    } else {
        src = wf2; dst = wf216; i = ((blk - 2048) << 10) + threadIdx.x * 4;
    }

    const float4* s4 = (const float4*)src + i;
    float4 v0 = s4[0], v1 = s4[1], v2 = s4[2], v3 = s4[3];
    uint4 o0, o1;
    o0.x = packh2(v0.x, v0.y); o0.y = packh2(v0.z, v0.w);
    o0.z = packh2(v1.x, v1.y); o0.w = packh2(v1.z, v1.w);
    o1.x = packh2(v2.x, v2.y); o1.y = packh2(v2.z, v2.w);
    o1.z = packh2(v3.x, v3.y); o1.w = packh2(v3.z, v3.w);

    __half* d;
    if (strided) {
        int r = i >> 8;
        int c = (i & 255) << 2;
        d = dst + (size_t)r * (3 * EMB) + c;
    } else {
        d = dst + (size_t)i * 4;
    }
    *(uint4*)d = o0;
    *(uint4*)(d + 8) = o1;
}

// -------------------- layernorm (fp16 output) -------------------------------
__global__ void __launch_bounds__(256)
ln16_kernel(const float* __restrict__ x, const float* __restrict__ sc,
            const float* __restrict__ sh, __half* __restrict__ out)
{
    __shared__ float red[8];
    __shared__ float stats[2];
    const int row = blockIdx.x, tid = threadIdx.x, lane = tid & 31, warp = tid >> 5;
    const float* xr = x + (size_t)row * EMB;
    float4 v = *(const float4*)(xr + tid * 4);

    float s = v.x + v.y + v.z + v.w;
    #pragma unroll
    for (int o = 16; o > 0; o >>= 1) s += __shfl_xor_sync(0xffffffffu, s, o);
    if (lane == 0) red[warp] = s;
    __syncthreads();
    if (tid == 0) {
        float t = 0.f;
        #pragma unroll
        for (int i = 0; i < 8; i++) t += red[i];
        stats[0] = t * (1.0f / EMB);
    }
    __syncthreads();
    const float mean = stats[0];
    float dx = v.x - mean, dy = v.y - mean, dz = v.z - mean, dw = v.w - mean;
    float ss = dx * dx + dy * dy + dz * dz + dw * dw;
    #pragma unroll
    for (int o = 16; o > 0; o >>= 1) ss += __shfl_xor_sync(0xffffffffu, ss, o);
    if (lane == 0) red[warp] = ss;
    __syncthreads();
    if (tid == 0) {
        float t = 0.f;
        #pragma unroll
        for (int i = 0; i < 8; i++) t += red[i];
        stats[1] = rsqrtf(t * (1.0f / EMB) + 1e-5f);
    }
    __syncthreads();
    const float rstd = stats[1];
    float4 scv = *(const float4*)(sc + tid * 4);
    float4 shv = *(const float4*)(sh + tid * 4);
    __half2 h0 = __floats2half2_rn(scv.x * dx * rstd + shv.x, scv.y * dy * rstd + shv.y);
    __half2 h1 = __floats2half2_rn(scv.z * dz * rstd + shv.z, scv.w * dw * rstd + shv.w);
    __half2* o = (__half2*)(out + (size_t)row * EMB + tid * 4);
    o[0] = h0; o[1] = h1;
}

// -------------------- shared GEMM constants --------------------
#define BK 64
#define A_ROW_B 144
#define B_ROW_B 272

enum { EP_H = 0, EP_GELU_H = 1, EP_RES_F = 2 };

// ==================== GEMM small: 128x128, 128 thr, 2 CTA/SM ===============
#define BM 128
#define BN 128
#define ASTG (BM * A_ROW_B)
#define BSTG (BK * B_ROW_B)
#define STGB (ASTG + BSTG)
#define GEMM_SMEM (3 * STGB)

__device__ __forceinline__ void fill_stage16(uint32_t sA, uint32_t sB,
                                             const __half* __restrict__ A,
                                             const __half* __restrict__ B,
                                             int bm, int bn, int N, int K, int kc, int tid)
{
    #pragma unroll
    for (int i = 0; i < 8; i++) {
        int e = tid + i * 128;
        int row = e >> 3, seg = e & 7;
        cpa16(sA + row * A_ROW_B + seg * 16,
              A + (size_t)(bm + row) * K + kc * BK + seg * 8);
    }
    #pragma unroll
    for (int i = 0; i < 8; i++) {
        int e = tid + i * 128;
        int row = e >> 4, seg = e & 15;
        cpa16(sB + row * B_ROW_B + seg * 16,
              B + (size_t)(kc * BK + row) * N + bn + seg * 8);
    }
}

template<int EPI>
__global__ void __launch_bounds__(128, 2)
gemm16(const __half* __restrict__ A, const __half* __restrict__ B,
       const float* __restrict__ bias, const float* __restrict__ R,
       void* __restrict__ Cv, int M, int N, int K)
{
    extern __shared__ char smem[];
    const uint32_t sbase = smem_u32(smem);

    const int tid = threadIdx.x, lane = tid & 31, warp = tid >> 5;
    const int bm = blockIdx.y * BM, bn = blockIdx.x * BN;
    const int wm = (warp & 1) * 64, wn = (warp >> 1) * 64;
    const int g = lane >> 2, t = lane & 3;
    const int NK = K / BK;

    float c[4][8][4];
    #pragma unroll
    for (int mt = 0; mt < 4; mt++)
        #pragma unroll
        for (int nt = 0; nt < 8; nt++)
            #pragma unroll
            for (int e = 0; e < 4; e++) c[mt][nt][e] = 0.f;

    fill_stage16(sbase,        sbase + ASTG,        A, B, bm, bn, N, K, 0, tid);
    CPA_COMMIT();
    fill_stage16(sbase + STGB, sbase + STGB + ASTG, A, B, bm, bn, N, K, 1, tid);
    CPA_COMMIT();

    const uint32_t laoff = (wm + (lane & 15)) * A_ROW_B + (lane >> 4) * 16;
    const uint32_t lboff = (lane & 15) * B_ROW_B + (lane >> 4) * 16 + wn * 2;

    int stg = 0;
    for (int kt = 0; kt < NK; kt++) {
        if (kt == NK - 1) cpa_wait<0>(); else cpa_wait<1>();
        __syncthreads();

        if (kt + 2 < NK) {
            int fs = kt + 2; fs -= (fs / 3) * 3;
            fill_stage16(sbase + fs * STGB, sbase + fs * STGB + ASTG,
                         A, B, bm, bn, N, K, kt + 2, tid);
            CPA_COMMIT();
        }

        const uint32_t sA = sbase + stg * STGB;
        const uint32_t sB = sA + ASTG;
        const uint32_t la = sA + laoff;
        const uint32_t lb = sB + lboff;

        #pragma unroll
        for (int ks = 0; ks < 4; ks++) {
            unsigned a[4][4], b[8][2];
            #pragma unroll
            for (int mt = 0; mt < 4; mt++)
                ldsm4(a[mt][0], a[mt][1], a[mt][2], a[mt][3],
                      la + mt * (16 * A_ROW_B) + ks * 32);
            #pragma unroll
            for (int np = 0; np < 4; np++) {
                unsigned r0, r1, r2, r3;
                ldsm4t(r0, r1, r2, r3, lb + ks * (16 * B_ROW_B) + np * 32);
                b[2 * np][0] = r0;     b[2 * np][1] = r1;
                b[2 * np + 1][0] = r2; b[2 * np + 1][1] = r3;
            }
            #pragma unroll
            for (int mt = 0; mt < 4; mt++)
                #pragma unroll
                for (int nt = 0; nt < 8; nt++)
                    mma16(c[mt][nt], a[mt], b[nt]);
        }

        stg++; if (stg == 3) stg = 0;
    }

    #pragma unroll
    for (int mt = 0; mt < 4; mt++) {
        #pragma unroll
        for (int nt = 0; nt < 8; nt++) {
            const int row0 = bm + wm + mt * 16 + g;
            const int col  = bn + wn + nt * 8 + t * 2;
            #pragma unroll
            for (int h = 0; h < 2; h++) {
                const int row = row0 + h * 8;
                float v0 = c[mt][nt][2 * h], v1 = c[mt][nt][2 * h + 1];
                const size_t off = (size_t)row * N + col;
                if (EPI == EP_H) {
                    *(__half2*)((__half*)Cv + off) = __floats2half2_rn(v0, v1);
                } else if (EPI == EP_GELU_H) {
                    float2 bb = *(const float2*)(bias + col);
                    *(__half2*)((__half*)Cv + off) =
                        __floats2half2_rn(gelu_f(v0 + bb.x), gelu_f(v1 + bb.y));
                } else {
                    float2 bb = *(const float2*)(bias + col);
                    float2 rr = *(const float2*)(R + off);
                    *(float2*)((float*)Cv + off) =
                        make_float2(v0 + bb.x + rr.x, v1 + bb.y + rr.y);
                }
            }
        }
    }
}

// ==================== GEMM big: 256x128, 256 thr, 1 CTA/SM =================
#define BM2 256
#define ASTG2 (BM2 * A_ROW_B)
#define STGB2 (ASTG2 + BSTG)
#define GEMM2_SMEM (3 * STGB2)

__device__ __forceinline__ void fill_stage16b(uint32_t sA, uint32_t sB,
                                              const __half* __restrict__ A,
                                              const __half* __restrict__ B,
                                              int bm, int bn, int N, int K, int kc, int tid)
{
    #pragma unroll
    for (int i = 0; i < 8; i++) {
        int e = tid + i * 256;
        int row = e >> 3, seg = e & 7;
        cpa16(sA + row * A_ROW_B + seg * 16,
              A + (size_t)(bm + row) * K + kc * BK + seg * 8);
    }
    #pragma unroll
    for (int i = 0; i < 4; i++) {
        int e = tid + i * 256;
        int row = e >> 4, seg = e & 15;
        cpa16(sB + row * B_ROW_B + seg * 16,
              B + (size_t)(kc * BK + row) * N + bn + seg * 8);
    }
}

template<int EPI>
__global__ void __launch_bounds__(256, 1)
gemm16b(const __half* __restrict__ A, const __half* __restrict__ B,
        const float* __restrict__ bias, const float* __restrict__ R,
        void* __restrict__ Cv, int M, int N, int K)
{
    extern __shared__ char smem[];
    const uint32_t sbase = smem_u32(smem);

    const int tid = threadIdx.x, lane = tid & 31, warp = tid >> 5;
    const int bm = blockIdx.y * BM2, bn = blockIdx.x * BN;
    const int wm = (warp & 3) * 64, wn = (warp >> 2) * 64;
    const int g = lane >> 2, t = lane & 3;
    const int NK = K / BK;

    float c[4][8][4];
    #pragma unroll
    for (int mt = 0; mt < 4; mt++)
        #pragma unroll
        for (int nt = 0; nt < 8; nt++)
            #pragma unroll
            for (int e = 0; e < 4; e++) c[mt][nt][e] = 0.f;

    fill_stage16b(sbase,         sbase + ASTG2,         A, B, bm, bn, N, K, 0, tid);
    CPA_COMMIT();
    fill_stage16b(sbase + STGB2, sbase + STGB2 + ASTG2, A, B, bm, bn, N, K, 1, tid);
    CPA_COMMIT();

    const uint32_t laoff = (wm + (lane & 15)) * A_ROW_B + (lane >> 4) * 16;
    const uint32_t lboff = (lane & 15) * B_ROW_B + (lane >> 4) * 16 + wn * 2;

    int stg = 0;
    for (int kt = 0; kt < NK; kt++) {
        if (kt == NK - 1) cpa_wait<0>(); else cpa_wait<1>();
        __syncthreads();

        if (kt + 2 < NK) {
            int fs = kt + 2; fs -= (fs / 3) * 3;
            fill_stage16b(sbase + fs * STGB2, sbase + fs * STGB2 + ASTG2,
                          A, B, bm, bn, N, K, kt + 2, tid);
            CPA_COMMIT();
        }

        const uint32_t sA = sbase + stg * STGB2;
        const uint32_t sB = sA + ASTG2;
        const uint32_t la = sA + laoff;
        const uint32_t lb = sB + lboff;

        #pragma unroll
        for (int ks = 0; ks < 4; ks++) {
            unsigned a[4][4], b[8][2];
            #pragma unroll
            for (int mt = 0; mt < 4; mt++)
                ldsm4(a[mt][0], a[mt][1], a[mt][2], a[mt][3],
                      la + mt * (16 * A_ROW_B) + ks * 32);
            #pragma unroll
            for (int np = 0; np < 4; np++) {
                unsigned r0, r1, r2, r3;
                ldsm4t(r0, r1, r2, r3, lb + ks * (16 * B_ROW_B) + np * 32);
                b[2 * np][0] = r0;     b[2 * np][1] = r1;
                b[2 * np + 1][0] = r2; b[2 * np + 1][1] = r3;
            }
            #pragma unroll
            for (int mt = 0; mt < 4; mt++)
                #pragma unroll
                for (int nt = 0; nt < 8; nt++)
                    mma16(c[mt][nt], a[mt], b[nt]);
        }

        stg++; if (stg == 3) stg = 0;
    }

    #pragma unroll
    for (int mt = 0; mt < 4; mt++) {
        #pragma unroll
        for (int nt = 0; nt < 8; nt++) {
            const int row0 = bm + wm + mt * 16 + g;
            const int col  = bn + wn + nt * 8 + t * 2;
            #pragma unroll
            for (int h = 0; h < 2; h++) {
                const int row = row0 + h * 8;
                float v0 = c[mt][nt][2 * h], v1 = c[mt][nt][2 * h + 1];
                const size_t off = (size_t)row * N + col;
                if (EPI == EP_H) {
                    *(__half2*)((__half*)Cv + off) = __floats2half2_rn(v0, v1);
                } else if (EPI == EP_GELU_H) {
                    float2 bb = *(const float2*)(bias + col);
                    *(__half2*)((__half*)Cv + off) =
                        __floats2half2_rn(gelu_f(v0 + bb.x), gelu_f(v1 + bb.y));
                } else {
                    float2 bb = *(const float2*)(bias + col);
                    float2 rr = *(const float2*)(R + off);
                    *(float2*)((float*)Cv + off) =
                        make_float2(v0 + bb.x + rr.x, v1 + bb.y + rr.y);
                }
            }
        }
    }
}

// -------------------- fp16 causal flash attention (Br=Bc=64, d=64) ---------
// exp2-domain softmax, scale folded into Q.
#define KROW 144
#define KVTILE (64 * KROW)
#define ATT_SMEM (KVTILE + 2 * 2 * KVTILE)

__global__ void __launch_bounds__(128, 3)
attn16(const __half* __restrict__ Qg, const __half* __restrict__ Kg,
       const __half* __restrict__ Vg, __half* __restrict__ O, int ldq)
{
    extern __shared__ char smem[];
    const uint32_t sbase = smem_u32(smem);
    const uint32_t sQ = sbase;

    const int tid = threadIdx.x, lane = tid & 31, warp = tid >> 5;
    const int g = lane >> 2, t = lane & 3;

    const int qt = gridDim.x - 1 - blockIdx.x;   // big tiles first
    const int bh = blockIdx.y;
    const int b = bh >> 4, h = bh & 15;
    const size_t qbase = (size_t)b * SEQ * ldq + (size_t)h * HDIM;
    const size_t obase = (size_t)b * SEQ * EMB + (size_t)h * HDIM;

    auto fill_kv = [&](int s, int j) {
        const uint32_t sK = sbase + KVTILE + s * (2 * KVTILE);
        const uint32_t sV = sK + KVTILE;
        #pragma unroll
        for (int i = 0; i < 4; i++) {
            int e = tid + i * 128;
            int row = e >> 3, seg = e & 7;
            size_t go = qbase + (size_t)(j * 64 + row) * ldq + seg * 8;
            cpa16(sK + row * KROW + seg * 16, Kg + go);
            cpa16(sV + row * KROW + seg * 16, Vg + go);
        }
    };

    fill_kv(0, 0);
    CPA_COMMIT();

    // Q tile -> smem, scaled by 0.125*log2(e) (exp2-domain softmax)
    const __half2 qsc = __half2half2(__float2half(0.18033688f));
    #pragma unroll
    for (int i = 0; i < 4; i++) {
        int e = tid + i * 128;
        int row = e >> 3, seg = e & 7;
        uint4 raw = *(const uint4*)(Qg + qbase + (size_t)(qt * 64 + row) * ldq + seg * 8);
        __half2* hp = (__half2*)&raw;
        hp[0] = __hmul2(hp[0], qsc);
        hp[1] = __hmul2(hp[1], qsc);
        hp[2] = __hmul2(hp[2], qsc);
        hp[3] = __hmul2(hp[3], qsc);
        *(uint4*)(smem + row * KROW + seg * 16) = raw;
    }
    __syncthreads();

    unsigned qa[4][4];
    {
        const uint32_t la = sQ + (warp * 16 + (lane & 15)) * KROW + (lane >> 4) * 16;
        #pragma unroll
        for (int ks = 0; ks < 4; ks++)
            ldsm4(qa[ks][0], qa[ks][1], qa[ks][2], qa[ks][3], la + ks * 32);
    }

    const uint32_t kboff = ((lane & 7) + ((lane >> 4) << 3)) * KROW + ((lane >> 3) & 1) * 16;
    const uint32_t vboff = (lane & 15) * KROW + (lane >> 4) * 16;

    float m0 = -1e30f, m1 = -1e30f, l0 = 0.f, l1 = 0.f;
    float o[8][4];
    #pragma unroll
    for (int dt = 0; dt < 8; dt++)
        #pragma unroll
        for (int e = 0; e < 4; e++) o[dt][e] = 0.f;

    const int r0g = qt * 64 + warp * 16 + g;

    for (int j = 0; j <= qt; j++) {
        if (j < qt) { fill_kv((j + 1) & 1, j + 1); CPA_COMMIT(); }
        if (j < qt) cpa_wait<1>(); else cpa_wait<0>();
        __syncthreads();

        const uint32_t sK = sbase + KVTILE + (j & 1) * (2 * KVTILE);
        const uint32_t sV = sK + KVTILE;

        float s[8][4];
        #pragma unroll
        for (int nt = 0; nt < 8; nt++)
            #pragma unroll
            for (int e = 0; e < 4; e++) s[nt][e] = 0.f;

        #pragma unroll
        for (int ks = 0; ks < 4; ks++) {
            unsigned kb[8][2];
            #pragma unroll
            for (int np = 0; np < 4; np++) {
                unsigned r0, r1, r2, r3;
                ldsm4(r0, r1, r2, r3, sK + kboff + np * (16 * KROW) + ks * 32);
                kb[2 * np][0] = r0;     kb[2 * np][1] = r1;
                kb[2 * np + 1][0] = r2; kb[2 * np + 1][1] = r3;
            }
            #pragma unroll
            for (int nt = 0; nt < 8; nt++)
                mma16(s[nt], qa[ks], kb[nt]);
        }

        // causal mask on diagonal tile (s already in exp2 domain)
        if (j == qt) {
            #pragma unroll
            for (int nt = 0; nt < 8; nt++) {
                int cb = j * 64 + nt * 8 + t * 2;
                if (cb     > r0g)     s[nt][0] = -1e30f;
                if (cb + 1 > r0g)     s[nt][1] = -1e30f;
                if (cb     > r0g + 8) s[nt][2] = -1e30f;
                if (cb + 1 > r0g + 8) s[nt][3] = -1e30f;
            }
        }

        float t0 = -1e30f, t1 = -1e30f;
        #pragma unroll
        for (int nt = 0; nt < 8; nt++) {
            t0 = fmaxf(t0, fmaxf(s[nt][0], s[nt][1]));
            t1 = fmaxf(t1, fmaxf(s[nt][2], s[nt][3]));
        }
        t0 = fmaxf(t0, __shfl_xor_sync(0xffffffffu, t0, 1));
        t0 = fmaxf(t0, __shfl_xor_sync(0xffffffffu, t0, 2));
        t1 = fmaxf(t1, __shfl_xor_sync(0xffffffffu, t1, 1));
        t1 = fmaxf(t1, __shfl_xor_sync(0xffffffffu, t1, 2));
        float mn0 = fmaxf(m0, t0), mn1 = fmaxf(m1, t1);
        float al0 = ex2f(m0 - mn0), al1 = ex2f(m1 - mn1);
        float su0 = 0.f, su1 = 0.f;
        #pragma unroll
        for (int nt = 0; nt < 8; nt++) {
            s[nt][0] = ex2f(s[nt][0] - mn0); su0 += s[nt][0];
            s[nt][1] = ex2f(s[nt][1] - mn0); su0 += s[nt][1];
            s[nt][2] = ex2f(s[nt][2] - mn1); su1 += s[nt][2];
            s[nt][3] = ex2f(s[nt][3] - mn1); su1 += s[nt][3];
        }
        su0 += __shfl_xor_sync(0xffffffffu, su0, 1);
        su0 += __shfl_xor_sync(0xffffffffu, su0, 2);
        su1 += __shfl_xor_sync(0xffffffffu, su1, 1);
        su1 += __shfl_xor_sync(0xffffffffu, su1, 2);
        l0 = l0 * al0 + su0; l1 = l1 * al1 + su1;
        m0 = mn0; m1 = mn1;
        #pragma unroll
        for (int dt = 0; dt < 8; dt++) {
            o[dt][0] *= al0; o[dt][1] *= al0;
            o[dt][2] *= al1; o[dt][3] *= al1;
        }

        #pragma unroll
        for (int ks = 0; ks < 4; ks++) {
            unsigned pa[4];
            pa[0] = packh2(s[2 * ks][0],     s[2 * ks][1]);
            pa[1] = packh2(s[2 * ks][2],     s[2 * ks][3]);
            pa[2] = packh2(s[2 * ks + 1][0], s[2 * ks + 1][1]);
            pa[3] = packh2(s[2 * ks + 1][2], s[2 * ks + 1][3]);
            unsigned vb[8][2];
            #pragma unroll
            for (int np = 0; np < 4; np++) {
                unsigned r0, r1, r2, r3;
                ldsm4t(r0, r1, r2, r3, sV + vboff + ks * (16 * KROW) + np * 32);
                vb[2 * np][0] = r0;     vb[2 * np][1] = r1;
                vb[2 * np + 1][0] = r2; vb[2 * np + 1][1] = r3;
            }
            #pragma unroll
            for (int nt = 0; nt < 8; nt++)
                mma16(o[nt], pa, vb[nt]);
        }

        __syncthreads();
    }

    const float i0 = 1.0f / l0, i1 = 1.0f / l1;
    #pragma unroll
    for (int dt = 0; dt < 8; dt++) {
        int col = dt * 8 + t * 2;
        size_t off0 = obase + (size_t)r0g * EMB + col;
        size_t off1 = obase + (size_t)(r0g + 8) * EMB + col;
        *(__half2*)(O + off0) = __floats2half2_rn(o[dt][0] * i0, o[dt][1] * i0);
        *(__half2*)(O + off1) = __floats2half2_rn(o[dt][2] * i1, o[dt][3] * i1);
    }
}

// -------------------- launch --------------------
extern "C" void kernel_launch(void* const* d_in, const int* in_sizes, int n_in,
                              void* d_out, int out_size)
{
    const float* x     = (const float*)d_in[0];
    const float* w_q   = (const float*)d_in[1];
    const float* w_k   = (const float*)d_in[2];
    const float* w_v   = (const float*)d_in[3];
    const float* w_o   = (const float*)d_in[4];
    const float* b_o   = (const float*)d_in[5];
    const float* ln1s  = (const float*)d_in[6];
    const float* ln1b  = (const float*)d_in[7];
    const float* ln2s  = (const float*)d_in[8];
    const float* ln2b  = (const float*)d_in[9];
    const float* w_ff1 = (const float*)d_in[10];
    const float* b_ff1 = (const float*)d_in[11];
    const float* w_ff2 = (const float*)d_in[12];
    const float* b_ff2 = (const float*)d_in[13];
    float* out = (float*)d_out;

    void *p;
    cudaGetSymbolAddress(&p, g_ln16);   __half* ln16   = (__half*)p;
    cudaGetSymbolAddress(&p, g_qkv16);  __half* qkv16  = (__half*)p;
    cudaGetSymbolAddress(&p, g_ctx16);  __half* ctx16  = (__half*)p;
    cudaGetSymbolAddress(&p, g_ff16);   __half* ff16   = (__half*)p;
    cudaGetSymbolAddress(&p, g_x1);     float*  x1     = (float*)p;
    cudaGetSymbolAddress(&p, g_wqkv16); __half* wqkv16 = (__half*)p;
    cudaGetSymbolAddress(&p, g_wo16);   __half* wo16   = (__half*)p;
    cudaGetSymbolAddress(&p, g_wf116);  __half* wf116  = (__half*)p;
    cudaGetSymbolAddress(&p, g_wf216);  __half* wf216  = (__half*)p;

    cudaFuncSetAttribute((const void*)gemm16<EP_RES_F>,
                         cudaFuncAttributeMaxDynamicSharedMemorySize, GEMM_SMEM);
    cudaFuncSetAttribute((const void*)gemm16b<EP_H>,
                         cudaFuncAttributeMaxDynamicSharedMemorySize, GEMM2_SMEM);
    cudaFuncSetAttribute((const void*)gemm16b<EP_GELU_H>,
                         cudaFuncAttributeMaxDynamicSharedMemorySize, GEMM2_SMEM);
    cudaFuncSetAttribute((const void*)attn16,
                         cudaFuncAttributeMaxDynamicSharedMemorySize, ATT_SMEM);

    // weights -> fp16, single fast launch
    round_all2<<<ROUND2_BLOCKS, 256>>>(w_q, w_k, w_v, w_o, w_ff1, w_ff2,
                                       wqkv16, wo16, wf116, wf216);

    // h = LN1(x)
    ln16_kernel<<<NROWS, 256>>>(x, ln1s, ln1b, ln16);
    // qkv = h @ [Wq|Wk|Wv]
    gemm16b<EP_H><<<dim3(3 * EMB / BN, NROWS / BM2), 256, GEMM2_SMEM>>>(
        ln16, wqkv16, nullptr, nullptr, qkv16, NROWS, 3 * EMB, EMB);
    // ctx = causal attention
    attn16<<<dim3(SEQ / 64, BATCH * NHEADS), 128, ATT_SMEM>>>(
        qkv16, qkv16 + EMB, qkv16 + 2 * EMB, ctx16, 3 * EMB);
    // x1 = x + ctx @ w_o + b_o
    gemm16<EP_RES_F><<<dim3(EMB / BN, NROWS / BM), 128, GEMM_SMEM>>>(
        ctx16, wo16, b_o, x, x1, NROWS, EMB, EMB);
    // h = LN2(x1)
    ln16_kernel<<<NROWS, 256>>>(x1, ln2s, ln2b, ln16);
    // ff = gelu(h @ w_ff1 + b_ff1)
    gemm16b<EP_GELU_H><<<dim3(FFDIM / BN, NROWS / BM2), 256, GEMM2_SMEM>>>(
        ln16, wf116, b_ff1, nullptr, ff16, NROWS, FFDIM, EMB);
    // out = x1 + ff @ w_ff2 + b_ff2
    gemm16<EP_RES_F><<<dim3(EMB / BN, NROWS / BM), 128, GEMM_SMEM>>>(
        ff16, wf216, b_ff2, x1, out, NROWS, EMB, FFDIM);
}